// round 10
// baseline (speedup 1.0000x reference)
#include <cuda_runtime.h>

#define BATCH 128
#define DIM   4096

typedef unsigned long long ull;

__device__ __forceinline__ void unpack2(ull v, float& lo, float& hi) {
    asm("mov.b64 {%0, %1}, %2;" : "=f"(lo), "=f"(hi) : "l"(v));
}
__device__ __forceinline__ ull ffma2(ull a, ull b, ull c) {
    ull d;
    asm("fma.rn.f32x2 %0, %1, %2, %3;" : "=l"(d) : "l"(a), "l"(b), "l"(c));
    return d;
}

// padded smem: float4-aligned, spreads strided groups across banks
__device__ __forceinline__ int phys(int i) {
    return i + 2 * (i >> 4) + 2 * (i >> 8);
}
#define BUF_F2 4640

// Swap-free complex MAC:
//   accA += (Ur,Ur)*(xr,xi) ; accB += (Ui,Ui)*(xr,xi)
//   yr = accA.lo - accB.hi ; yi = accA.hi + accB.lo
// Gate G[kp*16+k] = float4(Ur,Ur,Ui,Ui), Ur=ar, Ui=-ai.

__device__ __forceinline__ float2 combine(ull a, ull b) {
    float alo, ahi, blo, bhi;
    unpack2(a, alo, ahi);
    unpack2(b, blo, bhi);
    return make_float2(alo - bhi, ahi + blo);
}

struct Acc {
    ull A[4][2];   // [fiber][output 0: k=q, 1: k=q+8]
    ull B[4][2];
};
__device__ __forceinline__ void zero_acc(Acc& ac) {
    #pragma unroll
    for (int f = 0; f < 4; f++)
        #pragma unroll
        for (int o = 0; o < 2; o++) { ac.A[f][o] = 0ULL; ac.B[f][o] = 0ULL; }
}

// ---- contiguous-fiber contraction (steps 0 and 2) ----
// fibers at pb0 + 18*f, contracted index contiguous within fiber.
__device__ __forceinline__ void mac_contig(const float2* __restrict__ IN,
                                           const float4* __restrict__ G,
                                           int pb0, int q, Acc& ac)
{
    zero_acc(ac);
    #pragma unroll
    for (int half = 0; half < 2; half++) {
        // preload gates for kp = 8*half..+7, rows k=q and k=q+8
        ulonglong2 g[8][2];
        #pragma unroll
        for (int k8 = 0; k8 < 8; k8++) {
            const float4* Gr = G + (8 * half + k8) * 16 + q;
            g[k8][0] = *reinterpret_cast<const ulonglong2*>(Gr);
            g[k8][1] = *reinterpret_cast<const ulonglong2*>(Gr + 8);
        }
        #pragma unroll
        for (int kp2 = 0; kp2 < 4; kp2++) {
            float4 xv[4];
            #pragma unroll
            for (int f = 0; f < 4; f++)
                xv[f] = *reinterpret_cast<const float4*>(
                    IN + pb0 + 18 * f + 8 * half + 2 * kp2);
            #pragma unroll
            for (int sub = 0; sub < 2; sub++) {
                const int k8 = 2 * kp2 + sub;
                #pragma unroll
                for (int f = 0; f < 4; f++) {
                    ull xp = sub ? *(reinterpret_cast<ull*>(&xv[f]) + 1)
                                 : *reinterpret_cast<ull*>(&xv[f]);
                    ac.A[f][0] = ffma2(g[k8][0].x, xp, ac.A[f][0]);
                    ac.B[f][0] = ffma2(g[k8][0].y, xp, ac.B[f][0]);
                    ac.A[f][1] = ffma2(g[k8][1].x, xp, ac.A[f][1]);
                    ac.B[f][1] = ffma2(g[k8][1].y, xp, ac.B[f][1]);
                }
            }
        }
    }
}

// ---- strided contraction (step 1) ----
// 4 fibers adjacent in phys (+1); contracted index at phys stride 18.
__device__ __forceinline__ void mac_strided(const float2* __restrict__ IN,
                                            const float4* __restrict__ G,
                                            int pb, int q, Acc& ac)
{
    zero_acc(ac);
    #pragma unroll
    for (int half = 0; half < 2; half++) {
        ulonglong2 g[8][2];
        #pragma unroll
        for (int k8 = 0; k8 < 8; k8++) {
            const float4* Gr = G + (8 * half + k8) * 16 + q;
            g[k8][0] = *reinterpret_cast<const ulonglong2*>(Gr);
            g[k8][1] = *reinterpret_cast<const ulonglong2*>(Gr + 8);
        }
        #pragma unroll
        for (int k8 = 0; k8 < 8; k8++) {
            const int kp = 8 * half + k8;
            float4 v01 = *reinterpret_cast<const float4*>(IN + pb + kp * 18);
            float4 v23 = *reinterpret_cast<const float4*>(IN + pb + 2 + kp * 18);
            ull xp[4];
            xp[0] = *reinterpret_cast<ull*>(&v01);
            xp[1] = *(reinterpret_cast<ull*>(&v01) + 1);
            xp[2] = *reinterpret_cast<ull*>(&v23);
            xp[3] = *(reinterpret_cast<ull*>(&v23) + 1);
            #pragma unroll
            for (int f = 0; f < 4; f++) {
                ac.A[f][0] = ffma2(g[k8][0].x, xp[f], ac.A[f][0]);
                ac.B[f][0] = ffma2(g[k8][0].y, xp[f], ac.B[f][0]);
                ac.A[f][1] = ffma2(g[k8][1].x, xp[f], ac.A[f][1]);
                ac.B[f][1] = ffma2(g[k8][1].y, xp[f], ac.B[f][1]);
            }
        }
    }
}

__global__ __launch_bounds__(512, 1)
void ulayer_kernel(const float* __restrict__ thetas,
                   const float* __restrict__ evecs,
                   const float* __restrict__ evals,
                   const float* __restrict__ sreal,
                   const float* __restrict__ simag,
                   float* __restrict__ out)
{
    extern __shared__ float2 smem[];
    float2* A  = smem;                  // buffers ping-pong
    float2* Bv = smem + BUF_F2;
    float4* g4 = reinterpret_cast<float4*>(smem + 2 * BUF_F2); // 3*256

    const int t = threadIdx.x;
    const int b = blockIdx.x;

    // scratch overlay inside Bv (dead until step 0 writes Bv)
    float* Vs = reinterpret_cast<float*>(Bv);   // 16 rows, stride 17
    float* cs = reinterpret_cast<float*>(Bv) + 288;
    float* sn = reinterpret_cast<float*>(Bv) + 336;

    // ---- stage V and sincos ----
    if (t < 256) {
        Vs[(t >> 4) * 17 + (t & 15)] = evecs[t];
    }
    if (t >= 256 && t < 304) {
        int u = t - 256;
        int g = u >> 4, m = u & 15;
        float s, c;
        sincosf(thetas[g] * evals[m], &s, &c);
        cs[g * 16 + m] = c;
        sn[g * 16 + m] = s;
    }
    __syncthreads();

    // ---- build gates (t<256), layout G[kp*16+k] = (Ur,Ur,Ui,Ui) ----
    if (t < 256) {
        int k = t >> 4, kp = t & 15;
        #pragma unroll
        for (int g = 0; g < 3; g++) {
            float ar = 0.f, ai = 0.f;
            #pragma unroll
            for (int m = 0; m < 16; m++) {
                float p = Vs[k * 17 + m] * Vs[kp * 17 + m];
                ar += p * cs[g * 16 + m];
                ai += p * sn[g * 16 + m];
            }
            g4[g * 256 + kp * 16 + k] = make_float4(ar, ar, -ai, -ai);
        }
    }

    // ---- load state into A: vectorized LDG.128 + STS.128 ----
    {
        const float* srg = sreal + b * DIM;
        const float* sig = simag + b * DIM;
        #pragma unroll
        for (int w = 0; w < 2; w++) {
            int i0 = w * 2048 + 4 * t;
            float4 r  = *reinterpret_cast<const float4*>(srg + i0);
            float4 im = *reinterpret_cast<const float4*>(sig + i0);
            int p = phys(i0);             // i0 % 4 == 0 -> no pad crossing
            *reinterpret_cast<float4*>(A + p) =
                make_float4(r.x, im.x, r.y, im.y);
            *reinterpret_cast<float4*>(A + p + 2) =
                make_float4(r.z, im.z, r.w, im.w);
        }
    }
    __syncthreads();

    const int g = t >> 3, q = t & 7;    // g in [0,64), q in [0,8)
    const int ga = g >> 2;              // "a"-like coord of this group
    const int gb4 = 4 * (g & 3);        // low-coord base (multiple of 4)
    const int pb_contig = 72 * g + 2 * (g >> 2);  // fibers 4g..4g+3 base

    // ======== step 0: U2 contracts c; fibers (a,b), layout [a][b][kc] ========
    {
        Acc ac;
        mac_contig(A, g4 + 2 * 256, pb_contig, q, ac);
        #pragma unroll
        for (int f = 0; f < 4; f++) {
            Bv[pb_contig + 18 * f + q]     = combine(ac.A[f][0], ac.B[f][0]);
            Bv[pb_contig + 18 * f + q + 8] = combine(ac.A[f][1], ac.B[f][1]);
        }
    }
    __syncthreads();

    // ======== step 1: U1 contracts b; fibers (a,kc), kc = gb4..+3 ========
    // element addr = 290*a + 18*b + kc ; pb = 290*ga + gb4, stride 18
    {
        const int pb = 290 * ga + gb4;
        Acc ac;
        mac_strided(Bv, g4 + 1 * 256, pb, q, ac);
        // store to [kb][kc][a]: addr = 290*kb + 18*kc + a
        #pragma unroll
        for (int f = 0; f < 4; f++) {
            int col = 18 * (gb4 + f) + ga;
            A[290 * q + col]       = combine(ac.A[f][0], ac.B[f][0]);
            A[290 * (q + 8) + col] = combine(ac.A[f][1], ac.B[f][1]);
        }
    }
    __syncthreads();

    // ======== step 2: U0 contracts a; fibers (kb,kc), contiguous over a ====
    // fiber base = 290*kb + 18*kc ; group: kb = ga, kc = gb4..+3
    {
        Acc ac;
        mac_contig(A, g4 + 0 * 256, pb_contig, q, ac);
        // final out: d = ka*256 + kb*16 + kc ; float4 across kc = gb4..+3
        float* outr = out + b * DIM;
        float* outi = out + (size_t)BATCH * DIM + b * DIM;
        #pragma unroll
        for (int o = 0; o < 2; o++) {
            int ka = q + 8 * o;
            float2 y0 = combine(ac.A[0][o], ac.B[0][o]);
            float2 y1 = combine(ac.A[1][o], ac.B[1][o]);
            float2 y2 = combine(ac.A[2][o], ac.B[2][o]);
            float2 y3 = combine(ac.A[3][o], ac.B[3][o]);
            int d = ka * 256 + ga * 16 + gb4;
            *reinterpret_cast<float4*>(outr + d) =
                make_float4(y0.x, y1.x, y2.x, y3.x);
            *reinterpret_cast<float4*>(outi + d) =
                make_float4(y0.y, y1.y, y2.y, y3.y);
        }
    }
}

extern "C" void kernel_launch(void* const* d_in, const int* in_sizes, int n_in,
                              void* d_out, int out_size) {
    const float* thetas = (const float*)d_in[0];
    const float* evecs  = (const float*)d_in[1];
    const float* evals  = (const float*)d_in[2];
    const float* sreal  = (const float*)d_in[3];
    const float* simag  = (const float*)d_in[4];

    const int smem_bytes = 2 * BUF_F2 * sizeof(float2) + 3 * 256 * sizeof(float4);
    static bool attr_set = false;
    if (!attr_set) {
        cudaFuncSetAttribute(ulayer_kernel,
                             cudaFuncAttributeMaxDynamicSharedMemorySize,
                             smem_bytes);
        attr_set = true;
    }
    ulayer_kernel<<<BATCH, 512, smem_bytes>>>(thetas, evecs, evals,
                                              sreal, simag, (float*)d_out);
}

// round 11
// speedup vs baseline: 1.0025x; 1.0025x over previous
#include <cuda_runtime.h>

#define BATCH 128
#define DIM   4096

// padded smem layout: float4-aligned, spreads strided fibers across banks
__device__ __forceinline__ int phys(int i) {
    return i + 2 * (i >> 4) + 2 * (i >> 8);
}
#define BUF_F2 4640

// Scalar complex MAC: y += U*x with U = (Ur, Ui):
//   yr += Ur*xr - Ui*xi ; yi += Ur*xi + Ui*xr      (4 FFMA, neg is free)
// Gate storage (float2): gs[kp*16 + (k&3)*4 + (k>>2)] = (Ur, Ui)
// so thread q reads its 4 outputs k = q+4j as 32B contiguous (2 float4).

struct AccS {
    float yr[4][4];   // [fiber][j]  (output k = q + 4j)
    float yi[4][4];
};
__device__ __forceinline__ void zero_acc(AccS& a) {
    #pragma unroll
    for (int f = 0; f < 4; f++)
        #pragma unroll
        for (int j = 0; j < 4; j++) { a.yr[f][j] = 0.f; a.yi[f][j] = 0.f; }
}

// one kp step: gA = (Ur0,Ui0,Ur1,Ui1), gB = (Ur2,Ui2,Ur3,Ui3); x = (xr,xi)[4]
__device__ __forceinline__ void mac_kp(float4 gA, float4 gB,
                                       const float xr[4], const float xi[4],
                                       AccS& a)
{
    #pragma unroll
    for (int f = 0; f < 4; f++) {
        a.yr[f][0] = fmaf(gA.x, xr[f], a.yr[f][0]);
        a.yr[f][0] = fmaf(-gA.y, xi[f], a.yr[f][0]);
        a.yi[f][0] = fmaf(gA.x, xi[f], a.yi[f][0]);
        a.yi[f][0] = fmaf(gA.y, xr[f], a.yi[f][0]);

        a.yr[f][1] = fmaf(gA.z, xr[f], a.yr[f][1]);
        a.yr[f][1] = fmaf(-gA.w, xi[f], a.yr[f][1]);
        a.yi[f][1] = fmaf(gA.z, xi[f], a.yi[f][1]);
        a.yi[f][1] = fmaf(gA.w, xr[f], a.yi[f][1]);

        a.yr[f][2] = fmaf(gB.x, xr[f], a.yr[f][2]);
        a.yr[f][2] = fmaf(-gB.y, xi[f], a.yr[f][2]);
        a.yi[f][2] = fmaf(gB.x, xi[f], a.yi[f][2]);
        a.yi[f][2] = fmaf(gB.y, xr[f], a.yi[f][2]);

        a.yr[f][3] = fmaf(gB.z, xr[f], a.yr[f][3]);
        a.yr[f][3] = fmaf(-gB.w, xi[f], a.yr[f][3]);
        a.yi[f][3] = fmaf(gB.z, xi[f], a.yi[f][3]);
        a.yi[f][3] = fmaf(gB.w, xr[f], a.yi[f][3]);
    }
}

// ---- step 0: contracted index has logical stride 1 ----
// Thread (h, q): fibers 4h..4h+3 (fiber phys stride 18), outputs k = q+4j.
__device__ __forceinline__ void do_step0(const float2* __restrict__ IN,
                                         float2* __restrict__ OUT,
                                         const float4* __restrict__ Gf4,
                                         int h, int q)
{
    const int pb0 = 72 * h + 2 * (h >> 2);
    const float4* Gq = Gf4 + 2 * q;     // + kp*8 per kp

    AccS a;
    zero_acc(a);

    #pragma unroll
    for (int kp2 = 0; kp2 < 8; kp2++) {
        // one float4 per fiber covers kp = 2*kp2, 2*kp2+1
        float4 xv[4];
        #pragma unroll
        for (int f = 0; f < 4; f++)
            xv[f] = *reinterpret_cast<const float4*>(
                IN + pb0 + 18 * f + 2 * kp2);
        #pragma unroll
        for (int sub = 0; sub < 2; sub++) {
            const int kp = 2 * kp2 + sub;
            float4 gA = Gq[kp * 8];
            float4 gB = Gq[kp * 8 + 1];
            float xr[4], xi[4];
            #pragma unroll
            for (int f = 0; f < 4; f++) {
                xr[f] = sub ? xv[f].z : xv[f].x;
                xi[f] = sub ? xv[f].w : xv[f].y;
            }
            mac_kp(gA, gB, xr, xi, a);
        }
    }
    #pragma unroll
    for (int f = 0; f < 4; f++)
        #pragma unroll
        for (int j = 0; j < 4; j++)
            OUT[pb0 + 18 * f + (q + 4 * j)] =
                make_float2(a.yr[f][j], a.yi[f][j]);
}

// ---- steps 1 & 2: 4 fibers adjacent in phys (+1); PS = phys stride along kp
template<int PS>
__device__ __forceinline__ void do_step12(const float2* __restrict__ IN,
                                          float2* __restrict__ OUT,
                                          const float4* __restrict__ Gf4,
                                          int pb, int q)
{
    const float4* Gq = Gf4 + 2 * q;

    AccS a;
    zero_acc(a);

    #pragma unroll
    for (int kp = 0; kp < 16; kp++) {
        float4 v01 = *reinterpret_cast<const float4*>(IN + pb + kp * PS);
        float4 v23 = *reinterpret_cast<const float4*>(IN + pb + 2 + kp * PS);
        float4 gA = Gq[kp * 8];
        float4 gB = Gq[kp * 8 + 1];
        float xr[4] = { v01.x, v01.z, v23.x, v23.z };
        float xi[4] = { v01.y, v01.w, v23.y, v23.w };
        mac_kp(gA, gB, xr, xi, a);
    }
    // stores: fibers f,f+1 adjacent -> float4 store per (j, pair)
    #pragma unroll
    for (int j = 0; j < 4; j++) {
        int k = q + 4 * j;
        *reinterpret_cast<float4*>(OUT + pb + k * PS) =
            make_float4(a.yr[0][j], a.yi[0][j], a.yr[1][j], a.yi[1][j]);
        *reinterpret_cast<float4*>(OUT + pb + 2 + k * PS) =
            make_float4(a.yr[2][j], a.yi[2][j], a.yr[3][j], a.yi[3][j]);
    }
}

__global__ __launch_bounds__(256, 1)
void ulayer_kernel(const float* __restrict__ thetas,
                   const float* __restrict__ evecs,
                   const float* __restrict__ evals,
                   const float* __restrict__ sreal,
                   const float* __restrict__ simag,
                   float* __restrict__ out)
{
    extern __shared__ float2 smem[];
    float2* A  = smem;                  // BUF_F2 float2
    float2* Bv = smem + BUF_F2;         // BUF_F2 float2
    float2* gs = smem + 2 * BUF_F2;     // 3*256 float2 gates

    const int t = threadIdx.x;
    const int b = blockIdx.x;

    // scratch overlay inside Bv (dead until step 0 writes Bv, after syncs)
    float* Vs = reinterpret_cast<float*>(Bv);   // 16 rows, stride 17
    float* cs = reinterpret_cast<float*>(Bv) + 288;
    float* sn = reinterpret_cast<float*>(Bv) + 336;

    // ---- stage V and sincos ----
    {
        int j = t >> 4, m = t & 15;
        Vs[j * 17 + m] = evecs[t];               // V[j][m]
    }
    if (t < 48) {
        int g = t >> 4, m = t & 15;
        float s, c;
        sincosf(thetas[g] * evals[m], &s, &c);
        cs[g * 16 + m] = c;
        sn[g * 16 + m] = s;
    }
    __syncthreads();

    // ---- build gates: gs[g*256 + kp*16 + (k&3)*4 + (k>>2)] = (Ur, Ui) ----
    {
        int k = t >> 4, kp = t & 15;
        int slot = kp * 16 + (k & 3) * 4 + (k >> 2);
        #pragma unroll
        for (int g = 0; g < 3; g++) {
            float ar = 0.f, ai = 0.f;
            #pragma unroll
            for (int m = 0; m < 16; m++) {
                float p = Vs[k * 17 + m] * Vs[kp * 17 + m];
                ar += p * cs[g * 16 + m];
                ai += p * sn[g * 16 + m];
            }
            // U = Ur + i*Ui with Ur = ar, Ui = -ai
            gs[g * 256 + slot] = make_float2(ar, -ai);
        }
    }

    // ---- load state into A (concurrent with gate build) ----
    const float* srg = sreal + b * DIM;
    const float* sig = simag + b * DIM;
    #pragma unroll
    for (int w = 0; w < 16; w++) {
        int i = t + w * 256;
        A[phys(i)] = make_float2(srg[i], sig[i]);
    }
    __syncthreads();

    const int h = t >> 2, q = t & 3;   // h in [0,64), q in [0,4)
    const float4* g4 = reinterpret_cast<const float4*>(gs);  // 128 float4/gate

    // step 0: U2 on stride-1 index, fibers 4h..4h+3
    do_step0(A, Bv, g4 + 2 * 128, h, q);
    __syncthreads();

    // step 1: U1 on stride-16 index; fibers f0=4h..4h+3
    {
        int f0 = 4 * h;
        int pb = (f0 >> 4) * 290 + (f0 & 15);
        do_step12<18>(Bv, A, g4 + 1 * 128, pb, q);
    }
    __syncthreads();

    // step 2: U0 on stride-256 index; fibers f0=4h..4h+3
    {
        int f0 = 4 * h;
        int pb = f0 + 2 * (f0 >> 4);
        do_step12<290>(A, Bv, g4 + 0 * 128, pb, q);
    }
    __syncthreads();

    // ---- write output [2, BATCH, DIM] from Bv ----
    float* outr = out + b * DIM;
    float* outi = out + (size_t)BATCH * DIM + b * DIM;
    #pragma unroll
    for (int w = 0; w < 16; w++) {
        int i = t + w * 256;
        float2 v = Bv[phys(i)];
        outr[i] = v.x;
        outi[i] = v.y;
    }
}

extern "C" void kernel_launch(void* const* d_in, const int* in_sizes, int n_in,
                              void* d_out, int out_size) {
    const float* thetas = (const float*)d_in[0];
    const float* evecs  = (const float*)d_in[1];
    const float* evals  = (const float*)d_in[2];
    const float* sreal  = (const float*)d_in[3];
    const float* simag  = (const float*)d_in[4];

    const int smem_bytes = 2 * BUF_F2 * sizeof(float2) + 3 * 256 * sizeof(float2);
    static bool attr_set = false;
    if (!attr_set) {
        cudaFuncSetAttribute(ulayer_kernel,
                             cudaFuncAttributeMaxDynamicSharedMemorySize,
                             smem_bytes);
        attr_set = true;
    }
    ulayer_kernel<<<BATCH, 256, smem_bytes>>>(thetas, evecs, evals,
                                              sreal, simag, (float*)d_out);
}

// round 12
// speedup vs baseline: 1.0226x; 1.0201x over previous
#include <cuda_runtime.h>

#define BATCH 128
#define DIM   4096

// padded smem: float4-aligned, spreads strided groups across banks
__device__ __forceinline__ int phys(int i) {
    return i + 2 * (i >> 4) + 2 * (i >> 8);
}
#define BUF_F2 4640

// Scalar complex MAC with SPLIT accumulators (all FMAs independent):
//   yrA += Ur*xr ; yrB += Ui*xi ; yiA += Ur*xi ; yiB += Ui*xr
//   yr = yrA - yrB ; yi = yiA + yiB
// Gate float4 gs[kp*8+q] = (Ur_q, Ui_q, Ur_{q+8}, Ui_{q+8}), Ur=ar, Ui=-ai.

struct AccS {
    float rA[4][2], rB[4][2], iA[4][2], iB[4][2];  // [fiber][o], k = q + 8o
};
__device__ __forceinline__ void zero_acc(AccS& a) {
    #pragma unroll
    for (int f = 0; f < 4; f++)
        #pragma unroll
        for (int o = 0; o < 2; o++) {
            a.rA[f][o] = 0.f; a.rB[f][o] = 0.f;
            a.iA[f][o] = 0.f; a.iB[f][o] = 0.f;
        }
}
__device__ __forceinline__ void mac1(float4 g, float xr, float xi,
                                     AccS& a, int f) {
    a.rA[f][0] = fmaf(g.x, xr, a.rA[f][0]);
    a.rB[f][0] = fmaf(g.y, xi, a.rB[f][0]);
    a.iA[f][0] = fmaf(g.x, xi, a.iA[f][0]);
    a.iB[f][0] = fmaf(g.y, xr, a.iB[f][0]);
    a.rA[f][1] = fmaf(g.z, xr, a.rA[f][1]);
    a.rB[f][1] = fmaf(g.w, xi, a.rB[f][1]);
    a.iA[f][1] = fmaf(g.z, xi, a.iA[f][1]);
    a.iB[f][1] = fmaf(g.w, xr, a.iB[f][1]);
}
__device__ __forceinline__ float2 fin(const AccS& a, int f, int o) {
    return make_float2(a.rA[f][o] - a.rB[f][o], a.iA[f][o] + a.iB[f][o]);
}

// ---- contiguous-fiber contraction (steps 0 and 2) ----
__device__ __forceinline__ void mac_contig(const float2* __restrict__ IN,
                                           const float4* __restrict__ G,
                                           int pb0, int q, AccS& a)
{
    zero_acc(a);
    #pragma unroll
    for (int kp2 = 0; kp2 < 8; kp2++) {
        float4 xv[4];
        #pragma unroll
        for (int f = 0; f < 4; f++)
            xv[f] = *reinterpret_cast<const float4*>(
                IN + pb0 + 18 * f + 2 * kp2);
        #pragma unroll
        for (int sub = 0; sub < 2; sub++) {
            float4 g = G[(2 * kp2 + sub) * 8 + q];
            #pragma unroll
            for (int f = 0; f < 4; f++) {
                float xr = sub ? xv[f].z : xv[f].x;
                float xi = sub ? xv[f].w : xv[f].y;
                mac1(g, xr, xi, a, f);
            }
        }
    }
}

// ---- strided contraction (step 1): fibers adjacent (+1), kp stride 18 ----
__device__ __forceinline__ void mac_strided(const float2* __restrict__ IN,
                                            const float4* __restrict__ G,
                                            int pb, int q, AccS& a)
{
    zero_acc(a);
    #pragma unroll
    for (int kp = 0; kp < 16; kp++) {
        float4 v01 = *reinterpret_cast<const float4*>(IN + pb + kp * 18);
        float4 v23 = *reinterpret_cast<const float4*>(IN + pb + 2 + kp * 18);
        float4 g = G[kp * 8 + q];
        mac1(g, v01.x, v01.y, a, 0);
        mac1(g, v01.z, v01.w, a, 1);
        mac1(g, v23.x, v23.y, a, 2);
        mac1(g, v23.z, v23.w, a, 3);
    }
}

__global__ __launch_bounds__(512, 1)
void ulayer_kernel(const float* __restrict__ thetas,
                   const float* __restrict__ evecs,
                   const float* __restrict__ evals,
                   const float* __restrict__ sreal,
                   const float* __restrict__ simag,
                   float* __restrict__ out)
{
    extern __shared__ float2 smem[];
    float2* A  = smem;                  // ping-pong buffers
    float2* Bv = smem + BUF_F2;
    float2* gs2 = smem + 2 * BUF_F2;    // 3*256 float2 gates

    const int t = threadIdx.x;
    const int b = blockIdx.x;

    // scratch overlay inside Bv (dead until step 0 writes Bv)
    float* Vs = reinterpret_cast<float*>(Bv);   // 16 rows, stride 17
    float* cs = reinterpret_cast<float*>(Bv) + 288;
    float* sn = reinterpret_cast<float*>(Bv) + 336;

    // ---- stage V and sincos ----
    if (t < 256) {
        Vs[(t >> 4) * 17 + (t & 15)] = evecs[t];
    }
    if (t >= 256 && t < 304) {
        int u = t - 256;
        int g = u >> 4, m = u & 15;
        float s, c;
        sincosf(thetas[g] * evals[m], &s, &c);
        cs[g * 16 + m] = c;
        sn[g * 16 + m] = s;
    }
    __syncthreads();

    // ---- build gates: gs2[g*256 + 2*(kp*8 + (k&7)) + (k>>3)] = (Ur, Ui) ----
    if (t < 256) {
        int k = t >> 4, kp = t & 15;
        int slot = 2 * (kp * 8 + (k & 7)) + (k >> 3);
        #pragma unroll
        for (int g = 0; g < 3; g++) {
            float ar = 0.f, ai = 0.f;
            #pragma unroll
            for (int m = 0; m < 16; m++) {
                float p = Vs[k * 17 + m] * Vs[kp * 17 + m];
                ar += p * cs[g * 16 + m];
                ai += p * sn[g * 16 + m];
            }
            // U = ar - i*ai -> (Ur, Ui) = (ar, -ai)
            gs2[g * 256 + slot] = make_float2(ar, -ai);
        }
    }

    // ---- load state into A: vectorized LDG.128 + STS.128 ----
    {
        const float* srg = sreal + b * DIM;
        const float* sig = simag + b * DIM;
        #pragma unroll
        for (int w = 0; w < 2; w++) {
            int i0 = w * 2048 + 4 * t;
            float4 r  = *reinterpret_cast<const float4*>(srg + i0);
            float4 im = *reinterpret_cast<const float4*>(sig + i0);
            int p = phys(i0);             // i0 % 4 == 0 -> no pad crossing
            *reinterpret_cast<float4*>(A + p) =
                make_float4(r.x, im.x, r.y, im.y);
            *reinterpret_cast<float4*>(A + p + 2) =
                make_float4(r.z, im.z, r.w, im.w);
        }
    }
    __syncthreads();

    const float4* g4 = reinterpret_cast<const float4*>(gs2);  // 128 per gate
    const int g = t >> 3, q = t & 7;    // g in [0,64), q in [0,8)
    const int ga = g >> 2;
    const int gb4 = 4 * (g & 3);
    const int pb_contig = 72 * g + 2 * (g >> 2);  // fibers 4g..4g+3

    // ======== step 0: U2 contracts c; layout [a][b][kc] ========
    {
        AccS a;
        mac_contig(A, g4 + 2 * 128, pb_contig, q, a);
        #pragma unroll
        for (int f = 0; f < 4; f++) {
            Bv[pb_contig + 18 * f + q]     = fin(a, f, 0);
            Bv[pb_contig + 18 * f + q + 8] = fin(a, f, 1);
        }
    }
    __syncthreads();

    // ======== step 1: U1 contracts b; addr = 290*a + 18*b + kc ========
    {
        const int pb = 290 * ga + gb4;
        AccS a;
        mac_strided(Bv, g4 + 1 * 128, pb, q, a);
        // store to [kb][kc][a]
        #pragma unroll
        for (int f = 0; f < 4; f++) {
            int col = 18 * (gb4 + f) + ga;
            A[290 * q + col]       = fin(a, f, 0);
            A[290 * (q + 8) + col] = fin(a, f, 1);
        }
    }
    __syncthreads();

    // ======== step 2: U0 contracts a; fibers (kb,kc) contiguous ========
    {
        AccS a;
        mac_contig(A, g4 + 0 * 128, pb_contig, q, a);
        float* outr = out + b * DIM;
        float* outi = out + (size_t)BATCH * DIM + b * DIM;
        #pragma unroll
        for (int o = 0; o < 2; o++) {
            int ka = q + 8 * o;
            float2 y0 = fin(a, 0, o);
            float2 y1 = fin(a, 1, o);
            float2 y2 = fin(a, 2, o);
            float2 y3 = fin(a, 3, o);
            int d = ka * 256 + ga * 16 + gb4;
            *reinterpret_cast<float4*>(outr + d) =
                make_float4(y0.x, y1.x, y2.x, y3.x);
            *reinterpret_cast<float4*>(outi + d) =
                make_float4(y0.y, y1.y, y2.y, y3.y);
        }
    }
}

extern "C" void kernel_launch(void* const* d_in, const int* in_sizes, int n_in,
                              void* d_out, int out_size) {
    const float* thetas = (const float*)d_in[0];
    const float* evecs  = (const float*)d_in[1];
    const float* evals  = (const float*)d_in[2];
    const float* sreal  = (const float*)d_in[3];
    const float* simag  = (const float*)d_in[4];

    const int smem_bytes = 2 * BUF_F2 * sizeof(float2) + 3 * 256 * sizeof(float2);
    static bool attr_set = false;
    if (!attr_set) {
        cudaFuncSetAttribute(ulayer_kernel,
                             cudaFuncAttributeMaxDynamicSharedMemorySize,
                             smem_bytes);
        attr_set = true;
    }
    ulayer_kernel<<<BATCH, 512, smem_bytes>>>(thetas, evecs, evals,
                                              sreal, simag, (float*)d_out);
}